// round 8
// baseline (speedup 1.0000x reference)
#include <cuda_runtime.h>
#include <cstdint>
#include <math.h>

#define D_MODEL 1024
#define NHEADS  16
#define DK      64
#define BATCH   4
#define SEQ     2048
#define MROWS   (BATCH * SEQ)   // 8192

// Scratch (allocation-free rule: __device__ globals)
__device__ float g_Q[MROWS * D_MODEL];
__device__ float g_K[MROWS * D_MODEL];
__device__ float g_V[MROWS * D_MODEL];
__device__ float g_H[MROWS * D_MODEL];
__device__ float g_Xt[MROWS * D_MODEL];
__device__ float g_Wqt[D_MODEL * D_MODEL];
__device__ float g_Wkt[D_MODEL * D_MODEL];
__device__ float g_Wvt[D_MODEL * D_MODEL];
__device__ float g_Wht[D_MODEL * D_MODEL];

__device__ __forceinline__ uint32_t f2tf(float f) {
    uint32_t r;
    asm("cvt.rna.tf32.f32 %0, %1;" : "=r"(r) : "f"(f));
    return r;
}
__device__ __forceinline__ float tfr(float f) { return __uint_as_float(f2tf(f)); }

__device__ __forceinline__ void mma_tf32(float* d, const uint32_t* a, const uint32_t* b) {
    asm volatile(
        "mma.sync.aligned.m16n8k8.row.col.f32.tf32.tf32.f32 "
        "{%0,%1,%2,%3}, {%4,%5,%6,%7}, {%8,%9}, {%0,%1,%2,%3};"
        : "+f"(d[0]), "+f"(d[1]), "+f"(d[2]), "+f"(d[3])
        : "r"(a[0]), "r"(a[1]), "r"(a[2]), "r"(a[3]), "r"(b[0]), "r"(b[1]));
}

__device__ __forceinline__ uint32_t smem_u32(const void* p) {
    uint32_t a;
    asm("{ .reg .u64 t; cvta.to.shared.u64 t, %1; cvt.u32.u64 %0, t; }" : "=r"(a) : "l"(p));
    return a;
}
__device__ __forceinline__ void cp16(uint32_t dst, const void* src) {
    asm volatile("cp.async.cg.shared.global [%0], [%1], 16;" :: "r"(dst), "l"(src) : "memory");
}
#define CP_COMMIT asm volatile("cp.async.commit_group;" ::: "memory")
#define CP_WAIT1  asm volatile("cp.async.wait_group 1;" ::: "memory")
#define CP_WAIT0  asm volatile("cp.async.wait_group 0;" ::: "memory")

// Fast 2^t on FMA/ALU pipes (no MUFU). |err| ~2.4e-6 rel. t clamped to [-126,100].
__device__ __forceinline__ float exp2p(float t) {
    t = fmaxf(fminf(t, 100.0f), -126.0f);
    const float MAGIC = 12582912.0f;
    float tm = t + MAGIC;
    float n  = tm - MAGIC;
    float f  = t - n;
    float p  = 1.3333558146428443e-3f;
    p = fmaf(p, f, 9.6181291976036003e-3f);
    p = fmaf(p, f, 5.5504108664821580e-2f);
    p = fmaf(p, f, 2.4022650695910071e-1f);
    p = fmaf(p, f, 6.9314718055994531e-1f);
    p = fmaf(p, f, 1.0f);
    int sc = (__float_as_int(tm) + (127 - 0x4B400000)) << 23;
    return p * __int_as_float(sc);
}
#define L2E 1.4426950408889634f

// ---------------------------------------------------------------------------
// tf32 pre-rounding kernels
// ---------------------------------------------------------------------------
__global__ void cvt_tf32(float* __restrict__ dst, const float* __restrict__ src, int n4) {
    int i = blockIdx.x * blockDim.x + threadIdx.x;
    if (i < n4) {
        float4 v = ((const float4*)src)[i];
        ((uint4*)dst)[i] = make_uint4(f2tf(v.x), f2tf(v.y), f2tf(v.z), f2tf(v.w));
    }
}

__global__ void cvt_w4(float* d0, const float* s0, float* d1, const float* s1,
                       float* d2, const float* s2, float* d3, const float* s3, int n4) {
    int i = blockIdx.x * blockDim.x + threadIdx.x;
    const float* s; float* d;
    switch (blockIdx.y) {
        case 0:  s = s0; d = d0; break;
        case 1:  s = s1; d = d1; break;
        case 2:  s = s2; d = d2; break;
        default: s = s3; d = d3; break;
    }
    if (i < n4) {
        float4 v = ((const float4*)s)[i];
        ((uint4*)d)[i] = make_uint4(f2tf(v.x), f2tf(v.y), f2tf(v.z), f2tf(v.w));
    }
}

// ---------------------------------------------------------------------------
// TF32 GEMM core (NT), inputs pre-rounded tf32. BM=BN=128, BK=32, cp.async x2.
// ---------------------------------------------------------------------------
#define BM 128
#define BN 128
#define GNKT (D_MODEL / 32)   // 32

__device__ __forceinline__ void gemm_body(
    const float* __restrict__ A, const float* __restrict__ B,
    const float* __restrict__ bias, float* __restrict__ C,
    float scale, int outcvt, int m0, int n0, uint32_t* gsm)
{
    const uint32_t smemb = smem_u32(gsm);
    const int t = threadIdx.x, l = t & 31, w = t >> 5;
    const int wm = w & 1, wn = w >> 1;
    const int r = l >> 2, c = l & 3;

    uint32_t adst[4], bdst[4];
    const float *asrc[4], *bsrc[4];
#pragma unroll
    for (int i = 0; i < 4; i++) {
        const int ch = t + i * 256, rr = ch >> 3, g = ch & 7;
        const uint32_t d = (uint32_t)(rr * 32 + ((g ^ (rr & 7)) << 2)) * 4;
        adst[i] = d;
        bdst[i] = d + 16384;
        asrc[i] = A + (size_t)(m0 + rr) * D_MODEL + g * 4;
        bsrc[i] = B + (size_t)(n0 + rr) * D_MODEL + g * 4;
    }

    float acc[4][4][4];
#pragma unroll
    for (int mt = 0; mt < 4; mt++)
#pragma unroll
        for (int nt = 0; nt < 4; nt++)
#pragma unroll
            for (int q = 0; q < 4; q++) acc[mt][nt][q] = 0.f;

#pragma unroll
    for (int i = 0; i < 4; i++) { cp16(smemb + adst[i], asrc[i]); cp16(smemb + bdst[i], bsrc[i]); }
    CP_COMMIT;

    for (int kt = 0; kt < GNKT; kt++) {
        const int buf = kt & 1;
        if (kt + 1 < GNKT) {
            const int ko = (kt + 1) * 32;
            const uint32_t bo = (uint32_t)(buf ^ 1) * 32768u;
#pragma unroll
            for (int i = 0; i < 4; i++) {
                cp16(smemb + bo + adst[i], asrc[i] + ko);
                cp16(smemb + bo + bdst[i], bsrc[i] + ko);
            }
            CP_COMMIT;
            CP_WAIT1;
        } else {
            CP_WAIT0;
        }
        __syncthreads();

        const uint32_t* sa = gsm + buf * 8192;
        const uint32_t* sb = sa + 4096;
#pragma unroll
        for (int kk = 0; kk < 4; kk++) {
            const int g0 = 2 * kk, g1 = 2 * kk + 1;
            const int o0 = ((g0 ^ r) << 2) + c;
            const int o1 = ((g1 ^ r) << 2) + c;
            uint32_t af[4][4], bf[4][2];
#pragma unroll
            for (int mt = 0; mt < 4; mt++) {
                const int ra = (wm * 64 + mt * 16 + r) * 32;
                af[mt][0] = sa[ra + o0];
                af[mt][1] = sa[ra + 256 + o0];
                af[mt][2] = sa[ra + o1];
                af[mt][3] = sa[ra + 256 + o1];
            }
#pragma unroll
            for (int nt = 0; nt < 4; nt++) {
                const int rb = (wn * 32 + nt * 8 + r) * 32;
                bf[nt][0] = sb[rb + o0];
                bf[nt][1] = sb[rb + o1];
            }
#pragma unroll
            for (int mt = 0; mt < 4; mt++)
#pragma unroll
                for (int nt = 0; nt < 4; nt++)
                    mma_tf32(acc[mt][nt], af[mt], bf[nt]);
        }
        __syncthreads();
    }

    const int cc = c * 2;
#pragma unroll
    for (int mt = 0; mt < 4; mt++) {
        const int row0 = m0 + wm * 64 + mt * 16 + r;
#pragma unroll
        for (int nt = 0; nt < 4; nt++) {
            const int col = n0 + wn * 32 + nt * 8 + cc;
            float bx = 0.f, by = 0.f;
            if (bias) { bx = bias[col]; by = bias[col + 1]; }
            float v0 = acc[mt][nt][0] * scale + bx;
            float v1 = acc[mt][nt][1] * scale + by;
            float v2 = acc[mt][nt][2] * scale + bx;
            float v3 = acc[mt][nt][3] * scale + by;
            if (outcvt) { v0 = tfr(v0); v1 = tfr(v1); v2 = tfr(v2); v3 = tfr(v3); }
            *(float2*)(C + (size_t)row0 * D_MODEL + col) = make_float2(v0, v1);
            *(float2*)(C + (size_t)(row0 + 8) * D_MODEL + col) = make_float2(v2, v3);
        }
    }
}

// Fused QKV projection: blockIdx.x in [0,24): segment = bx>>3 selects W/C.
__global__ __launch_bounds__(256, 2) void gemm_qkv(
    const float* __restrict__ X,
    const float* __restrict__ Wq, const float* __restrict__ Wk, const float* __restrict__ Wv,
    float* __restrict__ Qo, float* __restrict__ Ko, float* __restrict__ Vo)
{
    extern __shared__ uint32_t gsm[];
    const int seg = blockIdx.x >> 3;
    const int n0  = (blockIdx.x & 7) * BN;
    const int m0  = blockIdx.y * BM;
    const float* B = (seg == 0) ? Wq : (seg == 1) ? Wk : Wv;
    float* C       = (seg == 0) ? Qo : (seg == 1) ? Ko : Vo;
    const float sc = (seg == 0) ? 0.125f : 1.0f;   // 1/sqrt(dk) folded into Q
    gemm_body(X, B, nullptr, C, sc, 1, m0, n0, gsm);
}

__global__ __launch_bounds__(256, 2) void gemm_out(
    const float* __restrict__ A, const float* __restrict__ B,
    const float* __restrict__ bias, float* __restrict__ C)
{
    extern __shared__ uint32_t gsm[];
    gemm_body(A, B, bias, C, 1.0f, 0, blockIdx.y * BM, blockIdx.x * BN, gsm);
}

// ---------------------------------------------------------------------------
// Tensor-core flash attention. BQ=256, 512 threads = 16 warps x 16 q-rows.
// Per-warp live set ~halved vs round 6/7 -> target <=128 regs -> 4 warps/SMSP.
// Per kv-chunk: S-chunk (8 MMAs) -> exp+permute -> PV-chunk (8 MMAs).
// ---------------------------------------------------------------------------
#define FBQ 256
#define FNT (SEQ / 64)   // 32
#define FTH 512

__global__ __launch_bounds__(FTH, 1) void flash_tc(
    const float* __restrict__ Q,
    const float* __restrict__ K,
    const float* __restrict__ V,
    float* __restrict__ O)
{
    extern __shared__ uint32_t fsm[];   // [2][ K 4096 | V 4096 ] u32
    const uint32_t smemb = smem_u32(fsm);
    const int t = threadIdx.x, l = t & 31, w = t >> 5;   // w: 0..15
    const int r = l >> 2, c = l & 3;
    const int q0 = blockIdx.x * FBQ;
    const size_t base = (size_t)blockIdx.z * SEQ * D_MODEL + (size_t)blockIdx.y * DK;

    // Q A-fragments: 16 q-rows per warp (pre-rounded tf32, scale folded)
    uint32_t qa[8][4];
    {
        const float* qp0 = Q + base + (size_t)(q0 + w * 16 + r) * D_MODEL;
        const float* qp1 = qp0 + 8 * D_MODEL;
#pragma unroll
        for (int kk = 0; kk < 8; kk++) {
            qa[kk][0] = __float_as_uint(qp0[kk * 8 + c]);
            qa[kk][1] = __float_as_uint(qp1[kk * 8 + c]);
            qa[kk][2] = __float_as_uint(qp0[kk * 8 + c + 4]);
            qa[kk][3] = __float_as_uint(qp1[kk * 8 + c + 4]);
        }
    }

    float o[8][4];
#pragma unroll
    for (int j = 0; j < 8; j++)
#pragma unroll
        for (int q = 0; q < 4; q++) o[j][q] = 0.f;
    float lsA = 0.f, lsB = 0.f;   // per-thread partials, reduced once at end

    // K loader slots: 2 x 16B chunks per thread (512 thr x 8 floats = 64x64)
    uint32_t kdst[2];
    const float* ksrc[2];
#pragma unroll
    for (int i = 0; i < 2; i++) {
        const int ch = t + i * FTH, rr = ch >> 4, g = ch & 15;
        kdst[i] = (uint32_t)(rr * 64 + (((g & 8) | ((g ^ (rr & 7)) & 7)) << 2)) * 4;
        ksrc[i] = K + base + (size_t)rr * D_MODEL + g * 4;
    }
    // V loader (transposed store): column d0, 8 kv rows per thread
    const int d0 = t & 63, kvg = t >> 6;   // kvg: 0..7
    uint32_t vdst[2];
#pragma unroll
    for (int p = 0; p < 2; p++) {
        const int g = kvg * 2 + p;
        vdst[p] = (uint32_t)(d0 * 64 + (((g & 8) | ((g ^ (d0 & 7)) & 7)) << 2));
    }
    const float* vsrc = V + base + (size_t)(kvg * 8) * D_MODEL + d0;

    uint32_t vr[8];
#pragma unroll
    for (int i = 0; i < 2; i++) cp16(smemb + kdst[i], ksrc[i]);
    CP_COMMIT;
#pragma unroll
    for (int j = 0; j < 8; j++) vr[j] = __float_as_uint(vsrc[(size_t)j * D_MODEL]);

    const int psrc = (l & ~3) | (c >> 1), psrc2 = psrc + 2;
    const bool podd = (c & 1);

    for (int kt = 0; kt < FNT; kt++) {
        const int buf = kt & 1;
        const bool pf = (kt + 1 < FNT);
        if (pf) {
            const size_t go = (size_t)(kt + 1) * 64 * D_MODEL;
            const uint32_t bo = (uint32_t)(buf ^ 1) * 32768u;
#pragma unroll
            for (int i = 0; i < 2; i++) cp16(smemb + bo + kdst[i], ksrc[i] + go);
            CP_COMMIT;
            CP_WAIT1;
        } else {
            CP_WAIT0;
        }
        {
            uint32_t* svw = fsm + buf * 8192 + 4096;
#pragma unroll
            for (int p = 0; p < 2; p++)
                *(uint4*)(svw + vdst[p]) =
                    make_uint4(vr[4 * p], vr[4 * p + 1], vr[4 * p + 2], vr[4 * p + 3]);
        }
        __syncthreads();
        if (pf) {
            const size_t go = (size_t)(kt + 1) * 64 * D_MODEL;
#pragma unroll
            for (int j = 0; j < 8; j++) vr[j] = __float_as_uint(vsrc[go + (size_t)j * D_MODEL]);
        }

        const uint32_t* sk = fsm + buf * 8192;
        const uint32_t* sv = sk + 4096;

        // ---- per kv-chunk: S-chunk -> exp+permute -> PV-chunk ----
#pragma unroll
        for (int n = 0; n < 8; n++) {
            float s[4] = {0.f, 0.f, 0.f, 0.f};
            const int krow = (n * 8 + r) * 64;
#pragma unroll
            for (int kk = 0; kk < 8; kk++) {
                const int g0 = 2 * kk, g1 = 2 * kk + 1;
                uint32_t bf[2];
                bf[0] = sk[krow + (((g0 & 8) | ((g0 ^ r) & 7)) << 2) + c];
                bf[1] = sk[krow + (((g1 & 8) | ((g1 ^ r) & 7)) << 2) + c];
                mma_tf32(s, qa[kk], bf);
            }

            // exp + permute (P D-frag -> A-frag)
            const float e0 = exp2p(s[0] * L2E);
            const float e1 = exp2p(s[1] * L2E);
            const float e2 = exp2p(s[2] * L2E);
            const float e3 = exp2p(s[3] * L2E);
            lsA += e0 + e1;
            lsB += e2 + e3;
            const float x0 = __shfl_sync(0xffffffffu, e0, psrc);
            const float x1 = __shfl_sync(0xffffffffu, e1, psrc);
            const float y0 = __shfl_sync(0xffffffffu, e0, psrc2);
            const float y1 = __shfl_sync(0xffffffffu, e1, psrc2);
            const float z0 = __shfl_sync(0xffffffffu, e2, psrc);
            const float z1 = __shfl_sync(0xffffffffu, e3, psrc);
            const float w0 = __shfl_sync(0xffffffffu, e2, psrc2);
            const float w1 = __shfl_sync(0xffffffffu, e3, psrc2);
            uint32_t pac[4];
            pac[0] = f2tf(podd ? x1 : x0);
            pac[1] = f2tf(podd ? z1 : z0);
            pac[2] = f2tf(podd ? y1 : y0);
            pac[3] = f2tf(podd ? w1 : w0);

            // O += P[:, n-chunk] x V[n-chunk, :]
            const int g0 = 2 * n, g1 = 2 * n + 1;
            const int vo0 = (((g0 & 8) | ((g0 ^ r) & 7)) << 2) + c;
            const int vo1 = (((g1 & 8) | ((g1 ^ r) & 7)) << 2) + c;
#pragma unroll
            for (int j = 0; j < 8; j++) {
                const int vrow = (j * 8 + r) * 64;
                uint32_t bf[2];
                bf[0] = sv[vrow + vo0];
                bf[1] = sv[vrow + vo1];
                mma_tf32(o[j], pac, bf);
            }
        }
        __syncthreads();
    }

    // ---- one-time l reduction, normalize + store (tf32-rounded) ----
#pragma unroll
    for (int off = 1; off <= 2; off <<= 1) {
        lsA += __shfl_xor_sync(0xffffffffu, lsA, off);
        lsB += __shfl_xor_sync(0xffffffffu, lsB, off);
    }
    const float i0 = 1.0f / lsA;
    const float i1 = 1.0f / lsB;
    float* r0p = O + base + (size_t)(q0 + w * 16 + r) * D_MODEL;
    float* r1p = r0p + 8 * D_MODEL;
#pragma unroll
    for (int j = 0; j < 8; j++) {
        const int col = j * 8 + c * 2;
        *(float2*)(r0p + col) = make_float2(tfr(o[j][0] * i0), tfr(o[j][1] * i0));
        *(float2*)(r1p + col) = make_float2(tfr(o[j][2] * i1), tfr(o[j][3] * i1));
    }
}

// ---------------------------------------------------------------------------
extern "C" void kernel_launch(void* const* d_in, const int* in_sizes, int n_in,
                              void* d_out, int out_size)
{
    const float* X   = (const float*)d_in[0];
    const float* W_q = (const float*)d_in[1];
    const float* W_k = (const float*)d_in[2];
    const float* W_v = (const float*)d_in[3];
    const float* W_h = (const float*)d_in[4];
    const float* b_h = (const float*)d_in[5];
    float* out = (float*)d_out;

    float *Qp, *Kp, *Vp, *Hp, *Xt, *Wq, *Wk, *Wv, *Wh;
    cudaGetSymbolAddress((void**)&Qp, g_Q);
    cudaGetSymbolAddress((void**)&Kp, g_K);
    cudaGetSymbolAddress((void**)&Vp, g_V);
    cudaGetSymbolAddress((void**)&Hp, g_H);
    cudaGetSymbolAddress((void**)&Xt, g_Xt);
    cudaGetSymbolAddress((void**)&Wq, g_Wqt);
    cudaGetSymbolAddress((void**)&Wk, g_Wkt);
    cudaGetSymbolAddress((void**)&Wv, g_Wvt);
    cudaGetSymbolAddress((void**)&Wh, g_Wht);

    const int GSM = 65536, FSM = 65536;
    cudaFuncSetAttribute(gemm_qkv, cudaFuncAttributeMaxDynamicSharedMemorySize, GSM);
    cudaFuncSetAttribute(gemm_out, cudaFuncAttributeMaxDynamicSharedMemorySize, GSM);
    cudaFuncSetAttribute(flash_tc, cudaFuncAttributeMaxDynamicSharedMemorySize, FSM);

    const int nX4 = MROWS * D_MODEL / 4;
    const int nW4 = D_MODEL * D_MODEL / 4;
    cvt_tf32<<<nX4 / 256, 256>>>(Xt, X, nX4);
    dim3 gw(nW4 / 256, 4);
    cvt_w4<<<gw, 256>>>(Wq, W_q, Wk, W_k, Wv, W_v, Wh, W_h, nW4);

    dim3 gq(24, MROWS / BM);             // fused QKV
    gemm_qkv<<<gq, 256, GSM>>>(Xt, Wq, Wk, Wv, Qp, Kp, Vp);

    dim3 gridF(SEQ / FBQ, NHEADS, BATCH);   // (8, 16, 4)
    flash_tc<<<gridF, FTH, FSM>>>(Qp, Kp, Vp, Hp);

    dim3 gg(D_MODEL / BN, MROWS / BM);
    gemm_out<<<gg, 256, GSM>>>(Hp, Wh, b_h, out);
}

// round 9
// speedup vs baseline: 1.0310x; 1.0310x over previous
#include <cuda_runtime.h>
#include <cstdint>
#include <math.h>

#define D_MODEL 1024
#define NHEADS  16
#define DK      64
#define BATCH   4
#define SEQ     2048
#define MROWS   (BATCH * SEQ)   // 8192

// Scratch (allocation-free rule: __device__ globals)
__device__ float g_Q[MROWS * D_MODEL];
__device__ float g_K[MROWS * D_MODEL];
__device__ float g_V[MROWS * D_MODEL];
__device__ float g_H[MROWS * D_MODEL];
__device__ float g_Xt[MROWS * D_MODEL];
__device__ float g_Wqt[D_MODEL * D_MODEL];
__device__ float g_Wkt[D_MODEL * D_MODEL];
__device__ float g_Wvt[D_MODEL * D_MODEL];
__device__ float g_Wht[D_MODEL * D_MODEL];

__device__ __forceinline__ uint32_t f2tf(float f) {
    uint32_t r;
    asm("cvt.rna.tf32.f32 %0, %1;" : "=r"(r) : "f"(f));
    return r;
}
__device__ __forceinline__ float tfr(float f) { return __uint_as_float(f2tf(f)); }

__device__ __forceinline__ void mma_tf32(float* d, const uint32_t* a, const uint32_t* b) {
    asm volatile(
        "mma.sync.aligned.m16n8k8.row.col.f32.tf32.tf32.f32 "
        "{%0,%1,%2,%3}, {%4,%5,%6,%7}, {%8,%9}, {%0,%1,%2,%3};"
        : "+f"(d[0]), "+f"(d[1]), "+f"(d[2]), "+f"(d[3])
        : "r"(a[0]), "r"(a[1]), "r"(a[2]), "r"(a[3]), "r"(b[0]), "r"(b[1]));
}

__device__ __forceinline__ uint32_t smem_u32(const void* p) {
    uint32_t a;
    asm("{ .reg .u64 t; cvta.to.shared.u64 t, %1; cvt.u32.u64 %0, t; }" : "=r"(a) : "l"(p));
    return a;
}
__device__ __forceinline__ void cp16(uint32_t dst, const void* src) {
    asm volatile("cp.async.cg.shared.global [%0], [%1], 16;" :: "r"(dst), "l"(src) : "memory");
}
#define CP_COMMIT asm volatile("cp.async.commit_group;" ::: "memory")
#define CP_WAIT1  asm volatile("cp.async.wait_group 1;" ::: "memory")
#define CP_WAIT0  asm volatile("cp.async.wait_group 0;" ::: "memory")

// Fast 2^t on FMA/ALU pipes (no MUFU). |err| ~2.4e-6 rel. t clamped to [-126,100].
__device__ __forceinline__ float exp2p(float t) {
    t = fmaxf(fminf(t, 100.0f), -126.0f);
    const float MAGIC = 12582912.0f;
    float tm = t + MAGIC;
    float n  = tm - MAGIC;
    float f  = t - n;
    float p  = 1.3333558146428443e-3f;
    p = fmaf(p, f, 9.6181291976036003e-3f);
    p = fmaf(p, f, 5.5504108664821580e-2f);
    p = fmaf(p, f, 2.4022650695910071e-1f);
    p = fmaf(p, f, 6.9314718055994531e-1f);
    p = fmaf(p, f, 1.0f);
    int sc = (__float_as_int(tm) + (127 - 0x4B400000)) << 23;
    return p * __int_as_float(sc);
}
#define L2E 1.4426950408889634f

// ---------------------------------------------------------------------------
// tf32 pre-rounding kernels
// ---------------------------------------------------------------------------
__global__ void cvt_tf32(float* __restrict__ dst, const float* __restrict__ src, int n4) {
    int i = blockIdx.x * blockDim.x + threadIdx.x;
    if (i < n4) {
        float4 v = ((const float4*)src)[i];
        ((uint4*)dst)[i] = make_uint4(f2tf(v.x), f2tf(v.y), f2tf(v.z), f2tf(v.w));
    }
}

__global__ void cvt_w4(float* d0, const float* s0, float* d1, const float* s1,
                       float* d2, const float* s2, float* d3, const float* s3, int n4) {
    int i = blockIdx.x * blockDim.x + threadIdx.x;
    const float* s; float* d;
    switch (blockIdx.y) {
        case 0:  s = s0; d = d0; break;
        case 1:  s = s1; d = d1; break;
        case 2:  s = s2; d = d2; break;
        default: s = s3; d = d3; break;
    }
    if (i < n4) {
        float4 v = ((const float4*)s)[i];
        ((uint4*)d)[i] = make_uint4(f2tf(v.x), f2tf(v.y), f2tf(v.z), f2tf(v.w));
    }
}

// ---------------------------------------------------------------------------
// TF32 GEMM core (NT), inputs pre-rounded tf32. BM=BN=128, BK=32, cp.async x2.
// ---------------------------------------------------------------------------
#define BM 128
#define BN 128
#define GNKT (D_MODEL / 32)   // 32

__device__ __forceinline__ void gemm_body(
    const float* __restrict__ A, const float* __restrict__ B,
    const float* __restrict__ bias, float* __restrict__ C,
    float scale, int outcvt, int m0, int n0, uint32_t* gsm)
{
    const uint32_t smemb = smem_u32(gsm);
    const int t = threadIdx.x, l = t & 31, w = t >> 5;
    const int wm = w & 1, wn = w >> 1;
    const int r = l >> 2, c = l & 3;

    uint32_t adst[4], bdst[4];
    const float *asrc[4], *bsrc[4];
#pragma unroll
    for (int i = 0; i < 4; i++) {
        const int ch = t + i * 256, rr = ch >> 3, g = ch & 7;
        const uint32_t d = (uint32_t)(rr * 32 + ((g ^ (rr & 7)) << 2)) * 4;
        adst[i] = d;
        bdst[i] = d + 16384;
        asrc[i] = A + (size_t)(m0 + rr) * D_MODEL + g * 4;
        bsrc[i] = B + (size_t)(n0 + rr) * D_MODEL + g * 4;
    }

    float acc[4][4][4];
#pragma unroll
    for (int mt = 0; mt < 4; mt++)
#pragma unroll
        for (int nt = 0; nt < 4; nt++)
#pragma unroll
            for (int q = 0; q < 4; q++) acc[mt][nt][q] = 0.f;

#pragma unroll
    for (int i = 0; i < 4; i++) { cp16(smemb + adst[i], asrc[i]); cp16(smemb + bdst[i], bsrc[i]); }
    CP_COMMIT;

    for (int kt = 0; kt < GNKT; kt++) {
        const int buf = kt & 1;
        if (kt + 1 < GNKT) {
            const int ko = (kt + 1) * 32;
            const uint32_t bo = (uint32_t)(buf ^ 1) * 32768u;
#pragma unroll
            for (int i = 0; i < 4; i++) {
                cp16(smemb + bo + adst[i], asrc[i] + ko);
                cp16(smemb + bo + bdst[i], bsrc[i] + ko);
            }
            CP_COMMIT;
            CP_WAIT1;
        } else {
            CP_WAIT0;
        }
        __syncthreads();

        const uint32_t* sa = gsm + buf * 8192;
        const uint32_t* sb = sa + 4096;
#pragma unroll
        for (int kk = 0; kk < 4; kk++) {
            const int g0 = 2 * kk, g1 = 2 * kk + 1;
            const int o0 = ((g0 ^ r) << 2) + c;
            const int o1 = ((g1 ^ r) << 2) + c;
            uint32_t af[4][4], bf[4][2];
#pragma unroll
            for (int mt = 0; mt < 4; mt++) {
                const int ra = (wm * 64 + mt * 16 + r) * 32;
                af[mt][0] = sa[ra + o0];
                af[mt][1] = sa[ra + 256 + o0];
                af[mt][2] = sa[ra + o1];
                af[mt][3] = sa[ra + 256 + o1];
            }
#pragma unroll
            for (int nt = 0; nt < 4; nt++) {
                const int rb = (wn * 32 + nt * 8 + r) * 32;
                bf[nt][0] = sb[rb + o0];
                bf[nt][1] = sb[rb + o1];
            }
#pragma unroll
            for (int mt = 0; mt < 4; mt++)
#pragma unroll
                for (int nt = 0; nt < 4; nt++)
                    mma_tf32(acc[mt][nt], af[mt], bf[nt]);
        }
        __syncthreads();
    }

    const int cc = c * 2;
#pragma unroll
    for (int mt = 0; mt < 4; mt++) {
        const int row0 = m0 + wm * 64 + mt * 16 + r;
#pragma unroll
        for (int nt = 0; nt < 4; nt++) {
            const int col = n0 + wn * 32 + nt * 8 + cc;
            float bx = 0.f, by = 0.f;
            if (bias) { bx = bias[col]; by = bias[col + 1]; }
            float v0 = acc[mt][nt][0] * scale + bx;
            float v1 = acc[mt][nt][1] * scale + by;
            float v2 = acc[mt][nt][2] * scale + bx;
            float v3 = acc[mt][nt][3] * scale + by;
            if (outcvt) { v0 = tfr(v0); v1 = tfr(v1); v2 = tfr(v2); v3 = tfr(v3); }
            *(float2*)(C + (size_t)row0 * D_MODEL + col) = make_float2(v0, v1);
            *(float2*)(C + (size_t)(row0 + 8) * D_MODEL + col) = make_float2(v2, v3);
        }
    }
}

// Fused QKV projection: blockIdx.x in [0,24): segment = bx>>3 selects W/C.
__global__ __launch_bounds__(256, 2) void gemm_qkv(
    const float* __restrict__ X,
    const float* __restrict__ Wq, const float* __restrict__ Wk, const float* __restrict__ Wv,
    float* __restrict__ Qo, float* __restrict__ Ko, float* __restrict__ Vo)
{
    extern __shared__ uint32_t gsm[];
    const int seg = blockIdx.x >> 3;
    const int n0  = (blockIdx.x & 7) * BN;
    const int m0  = blockIdx.y * BM;
    const float* B = (seg == 0) ? Wq : (seg == 1) ? Wk : Wv;
    float* C       = (seg == 0) ? Qo : (seg == 1) ? Ko : Vo;
    const float sc = (seg == 0) ? 0.125f : 1.0f;   // 1/sqrt(dk) folded into Q
    gemm_body(X, B, nullptr, C, sc, 1, m0, n0, gsm);
}

__global__ __launch_bounds__(256, 2) void gemm_out(
    const float* __restrict__ A, const float* __restrict__ B,
    const float* __restrict__ bias, float* __restrict__ C)
{
    extern __shared__ uint32_t gsm[];
    gemm_body(A, B, bias, C, 1.0f, 0, blockIdx.y * BM, blockIdx.x * BN, gsm);
}

// ---------------------------------------------------------------------------
// Tensor-core flash attention. BQ=256, 256 threads = 8 warps x 32 q-rows
// (fat warps: best K/V reuse). S computed for TWO kv-chunks in flight
// (s[2][2][4] = 16 regs) -> 4 independent S MMA chains/warp, no spills.
// ---------------------------------------------------------------------------
#define FBQ 256
#define FNT (SEQ / 64)   // 32
#define FTH 256

__global__ __launch_bounds__(FTH, 1) void flash_tc(
    const float* __restrict__ Q,
    const float* __restrict__ K,
    const float* __restrict__ V,
    float* __restrict__ O)
{
    extern __shared__ uint32_t fsm[];   // [2][ K 4096 | V 4096 ] u32
    const uint32_t smemb = smem_u32(fsm);
    const int t = threadIdx.x, l = t & 31, w = t >> 5;   // w: 0..7
    const int r = l >> 2, c = l & 3;
    const int q0 = blockIdx.x * FBQ;
    const size_t base = (size_t)blockIdx.z * SEQ * D_MODEL + (size_t)blockIdx.y * DK;

    // Q A-fragments: 32 q-rows per warp (2 m-tiles), pre-rounded tf32
    uint32_t qa[2][8][4];
#pragma unroll
    for (int mi = 0; mi < 2; mi++) {
        const float* qp0 = Q + base + (size_t)(q0 + w * 32 + mi * 16 + r) * D_MODEL;
        const float* qp1 = qp0 + 8 * D_MODEL;
#pragma unroll
        for (int kk = 0; kk < 8; kk++) {
            qa[mi][kk][0] = __float_as_uint(qp0[kk * 8 + c]);
            qa[mi][kk][1] = __float_as_uint(qp1[kk * 8 + c]);
            qa[mi][kk][2] = __float_as_uint(qp0[kk * 8 + c + 4]);
            qa[mi][kk][3] = __float_as_uint(qp1[kk * 8 + c + 4]);
        }
    }

    float o[2][8][4];
#pragma unroll
    for (int mi = 0; mi < 2; mi++)
#pragma unroll
        for (int j = 0; j < 8; j++)
#pragma unroll
            for (int q = 0; q < 4; q++) o[mi][j][q] = 0.f;
    float lsA[2] = {0.f, 0.f};
    float lsB[2] = {0.f, 0.f};

    // K loader slots: 4 x 16B chunks per thread (256 thr)
    uint32_t kdst[4];
    const float* ksrc[4];
#pragma unroll
    for (int i = 0; i < 4; i++) {
        const int ch = t + i * FTH, rr = ch >> 4, g = ch & 15;
        kdst[i] = (uint32_t)(rr * 64 + (((g & 8) | ((g ^ (rr & 7)) & 7)) << 2)) * 4;
        ksrc[i] = K + base + (size_t)rr * D_MODEL + g * 4;
    }
    // V loader (transposed store): column d0, 16 kv rows per thread
    const int d0 = t & 63, kvg = t >> 6;   // kvg: 0..3
    uint32_t vdst[4];
#pragma unroll
    for (int p = 0; p < 4; p++) {
        const int g = kvg * 4 + p;
        vdst[p] = (uint32_t)(d0 * 64 + (((g & 8) | ((g ^ (d0 & 7)) & 7)) << 2));
    }
    const float* vsrc = V + base + (size_t)(kvg * 16) * D_MODEL + d0;

    uint32_t vr[16];
#pragma unroll
    for (int i = 0; i < 4; i++) cp16(smemb + kdst[i], ksrc[i]);
    CP_COMMIT;
#pragma unroll
    for (int j = 0; j < 16; j++) vr[j] = __float_as_uint(vsrc[(size_t)j * D_MODEL]);

    const int psrc = (l & ~3) | (c >> 1), psrc2 = psrc + 2;
    const bool podd = (c & 1);

    for (int kt = 0; kt < FNT; kt++) {
        const int buf = kt & 1;
        const bool pf = (kt + 1 < FNT);
        if (pf) {
            const size_t go = (size_t)(kt + 1) * 64 * D_MODEL;
            const uint32_t bo = (uint32_t)(buf ^ 1) * 32768u;
#pragma unroll
            for (int i = 0; i < 4; i++) cp16(smemb + bo + kdst[i], ksrc[i] + go);
            CP_COMMIT;
            CP_WAIT1;
        } else {
            CP_WAIT0;
        }
        {
            uint32_t* svw = fsm + buf * 8192 + 4096;
#pragma unroll
            for (int p = 0; p < 4; p++)
                *(uint4*)(svw + vdst[p]) =
                    make_uint4(vr[4 * p], vr[4 * p + 1], vr[4 * p + 2], vr[4 * p + 3]);
        }
        __syncthreads();
        if (pf) {
            const size_t go = (size_t)(kt + 1) * 64 * D_MODEL;
#pragma unroll
            for (int j = 0; j < 16; j++) vr[j] = __float_as_uint(vsrc[go + (size_t)j * D_MODEL]);
        }

        const uint32_t* sk = fsm + buf * 8192;
        const uint32_t* sv = sk + 4096;

        // ---- per chunk-PAIR: S (4 indep chains) -> exp+permute -> PV ----
#pragma unroll
        for (int np = 0; np < 4; np++) {
            const int n0c = 2 * np, n1c = 2 * np + 1;
            float s[2][2][4];   // [chunk][mi][4]
#pragma unroll
            for (int ch = 0; ch < 2; ch++)
#pragma unroll
                for (int mi = 0; mi < 2; mi++)
#pragma unroll
                    for (int q = 0; q < 4; q++) s[ch][mi][q] = 0.f;

            const int krow0 = (n0c * 8 + r) * 64;
            const int krow1 = (n1c * 8 + r) * 64;
#pragma unroll
            for (int kk = 0; kk < 8; kk++) {
                const int g0 = 2 * kk, g1 = 2 * kk + 1;
                const int off0 = (((g0 & 8) | ((g0 ^ r) & 7)) << 2) + c;
                const int off1 = (((g1 & 8) | ((g1 ^ r) & 7)) << 2) + c;
                uint32_t bf0[2], bf1[2];
                bf0[0] = sk[krow0 + off0];
                bf0[1] = sk[krow0 + off1];
                bf1[0] = sk[krow1 + off0];
                bf1[1] = sk[krow1 + off1];
                mma_tf32(s[0][0], qa[0][kk], bf0);
                mma_tf32(s[0][1], qa[1][kk], bf0);
                mma_tf32(s[1][0], qa[0][kk], bf1);
                mma_tf32(s[1][1], qa[1][kk], bf1);
            }

            // exp + permute (4 independent groups)
            uint32_t pac[2][2][4];
#pragma unroll
            for (int ch = 0; ch < 2; ch++) {
#pragma unroll
                for (int mi = 0; mi < 2; mi++) {
                    const float e0 = exp2p(s[ch][mi][0] * L2E);
                    const float e1 = exp2p(s[ch][mi][1] * L2E);
                    const float e2 = exp2p(s[ch][mi][2] * L2E);
                    const float e3 = exp2p(s[ch][mi][3] * L2E);
                    lsA[mi] += e0 + e1;
                    lsB[mi] += e2 + e3;
                    const float x0 = __shfl_sync(0xffffffffu, e0, psrc);
                    const float x1 = __shfl_sync(0xffffffffu, e1, psrc);
                    const float y0 = __shfl_sync(0xffffffffu, e0, psrc2);
                    const float y1 = __shfl_sync(0xffffffffu, e1, psrc2);
                    const float z0 = __shfl_sync(0xffffffffu, e2, psrc);
                    const float z1 = __shfl_sync(0xffffffffu, e3, psrc);
                    const float w0 = __shfl_sync(0xffffffffu, e2, psrc2);
                    const float w1 = __shfl_sync(0xffffffffu, e3, psrc2);
                    pac[ch][mi][0] = f2tf(podd ? x1 : x0);
                    pac[ch][mi][1] = f2tf(podd ? z1 : z0);
                    pac[ch][mi][2] = f2tf(podd ? y1 : y0);
                    pac[ch][mi][3] = f2tf(podd ? w1 : w0);
                }
            }

            // O += P[:, pair] x V[pair, :]
            const int gA0 = 2 * n0c, gA1 = 2 * n0c + 1;
            const int gB0 = 2 * n1c, gB1 = 2 * n1c + 1;
            const int voA0 = (((gA0 & 8) | ((gA0 ^ r) & 7)) << 2) + c;
            const int voA1 = (((gA1 & 8) | ((gA1 ^ r) & 7)) << 2) + c;
            const int voB0 = (((gB0 & 8) | ((gB0 ^ r) & 7)) << 2) + c;
            const int voB1 = (((gB1 & 8) | ((gB1 ^ r) & 7)) << 2) + c;
#pragma unroll
            for (int j = 0; j < 8; j++) {
                const int vrow = (j * 8 + r) * 64;
                uint32_t bfA[2], bfB[2];
                bfA[0] = sv[vrow + voA0];
                bfA[1] = sv[vrow + voA1];
                bfB[0] = sv[vrow + voB0];
                bfB[1] = sv[vrow + voB1];
                mma_tf32(o[0][j], pac[0][0], bfA);
                mma_tf32(o[1][j], pac[0][1], bfA);
                mma_tf32(o[0][j], pac[1][0], bfB);
                mma_tf32(o[1][j], pac[1][1], bfB);
            }
        }
        __syncthreads();
    }

    // ---- one-time l reduction, normalize + store (tf32-rounded) ----
#pragma unroll
    for (int mi = 0; mi < 2; mi++) {
#pragma unroll
        for (int off = 1; off <= 2; off <<= 1) {
            lsA[mi] += __shfl_xor_sync(0xffffffffu, lsA[mi], off);
            lsB[mi] += __shfl_xor_sync(0xffffffffu, lsB[mi], off);
        }
    }
#pragma unroll
    for (int mi = 0; mi < 2; mi++) {
        const float i0 = 1.0f / lsA[mi];
        const float i1 = 1.0f / lsB[mi];
        float* r0p = O + base + (size_t)(q0 + w * 32 + mi * 16 + r) * D_MODEL;
        float* r1p = r0p + 8 * D_MODEL;
#pragma unroll
        for (int j = 0; j < 8; j++) {
            const int col = j * 8 + c * 2;
            *(float2*)(r0p + col) = make_float2(tfr(o[mi][j][0] * i0), tfr(o[mi][j][1] * i0));
            *(float2*)(r1p + col) = make_float2(tfr(o[mi][j][2] * i1), tfr(o[mi][j][3] * i1));
        }
    }
}

// ---------------------------------------------------------------------------
extern "C" void kernel_launch(void* const* d_in, const int* in_sizes, int n_in,
                              void* d_out, int out_size)
{
    const float* X   = (const float*)d_in[0];
    const float* W_q = (const float*)d_in[1];
    const float* W_k = (const float*)d_in[2];
    const float* W_v = (const float*)d_in[3];
    const float* W_h = (const float*)d_in[4];
    const float* b_h = (const float*)d_in[5];
    float* out = (float*)d_out;

    float *Qp, *Kp, *Vp, *Hp, *Xt, *Wq, *Wk, *Wv, *Wh;
    cudaGetSymbolAddress((void**)&Qp, g_Q);
    cudaGetSymbolAddress((void**)&Kp, g_K);
    cudaGetSymbolAddress((void**)&Vp, g_V);
    cudaGetSymbolAddress((void**)&Hp, g_H);
    cudaGetSymbolAddress((void**)&Xt, g_Xt);
    cudaGetSymbolAddress((void**)&Wq, g_Wqt);
    cudaGetSymbolAddress((void**)&Wk, g_Wkt);
    cudaGetSymbolAddress((void**)&Wv, g_Wvt);
    cudaGetSymbolAddress((void**)&Wh, g_Wht);

    const int GSM = 65536, FSM = 65536;
    cudaFuncSetAttribute(gemm_qkv, cudaFuncAttributeMaxDynamicSharedMemorySize, GSM);
    cudaFuncSetAttribute(gemm_out, cudaFuncAttributeMaxDynamicSharedMemorySize, GSM);
    cudaFuncSetAttribute(flash_tc, cudaFuncAttributeMaxDynamicSharedMemorySize, FSM);

    const int nX4 = MROWS * D_MODEL / 4;
    const int nW4 = D_MODEL * D_MODEL / 4;
    cvt_tf32<<<nX4 / 256, 256>>>(Xt, X, nX4);
    dim3 gw(nW4 / 256, 4);
    cvt_w4<<<gw, 256>>>(Wq, W_q, Wk, W_k, Wv, W_v, Wh, W_h, nW4);

    dim3 gq(24, MROWS / BM);             // fused QKV
    gemm_qkv<<<gq, 256, GSM>>>(Xt, Wq, Wk, Wv, Qp, Kp, Vp);

    dim3 gridF(SEQ / FBQ, NHEADS, BATCH);   // (8, 16, 4)
    flash_tc<<<gridF, FTH, FSM>>>(Qp, Kp, Vp, Hp);

    dim3 gg(D_MODEL / BN, MROWS / BM);
    gemm_out<<<gg, 256, GSM>>>(Hp, Wh, b_h, out);
}